// round 15
// baseline (speedup 1.0000x reference)
#include <cuda_runtime.h>
#include <cuda_fp16.h>

// Problem constants (fixed by the reference setup)
#define BB   2
#define CH   64
#define NH   8
#define DH   8
#define HW   48
#define LL   2304            // HW*HW
#define BCHL (BB*CH*LL)      // 294912

#define LOG2E 1.4426950408889634f

#define EX2F(r,x)     asm("ex2.approx.ftz.f32 %0,%1;"  : "=f"(r) : "f"(x))
#define CVT_TF32(u,x) asm("cvt.rna.tf32.f32 %0,%1;"    : "=r"(u) : "f"(x))
// d = {hi=cvt(a), lo=cvt(b)}
#define PACK_F16X2(d,a,b) asm("cvt.rn.f16x2.f32 %0,%1,%2;" : "=r"(d) : "f"(a), "f"(b))

#define MMA_TF32(d0,d1,d2,d3,a0,a1,a2,a3,b0,b1) \
  asm volatile("mma.sync.aligned.m16n8k8.row.col.f32.tf32.tf32.f32 " \
    "{%0,%1,%2,%3},{%4,%5,%6,%7},{%8,%9},{%0,%1,%2,%3};" \
    : "+f"(d0),"+f"(d1),"+f"(d2),"+f"(d3) \
    : "r"(a0),"r"(a1),"r"(a2),"r"(a3),"r"(b0),"r"(b1))

#define MMA_F16(d0,d1,d2,d3,a0,a1,a2,a3,b0,b1) \
  asm volatile("mma.sync.aligned.m16n8k16.row.col.f32.f16.f16.f32 " \
    "{%0,%1,%2,%3},{%4,%5,%6,%7},{%8,%9},{%0,%1,%2,%3};" \
    : "+f"(d0),"+f"(d1),"+f"(d2),"+f"(d3) \
    : "r"(a0),"r"(a1),"r"(a2),"r"(a3),"r"(b0),"r"(b1))

typedef unsigned int u32;

// Scratch (device globals — no allocation allowed)
__device__ float g_q [BCHL];          // q * d^-0.5 * log2(e)  (for EX2)
__device__ float g_k [BCHL];
__device__ float g_v [BCHL];
__device__ float g_Z [2][BB*NH][LL];  // 2 q-split partials
__device__ float g_op[2][BCHL];

// ---------------------------------------------------------------------------
// K1: q/k/v 1x1 convs as tf32 tensor GEMM.  grid = 288 x 384 (12 warps).
// 16 columns per block (2 blocks/SM for latency overlap).  Warp
// (m_idx = wid>>2 in {q,k,v}, mtile = wid&3) holds W A-fragments (hi/lo)
// in registers; X tile staged hi/lo in SMEM (pad 40 = conflict-free frags).
// 3-term split: Wh*Xh + Wh*Xl + Wl*Xh  (error ~2^-22).
// ---------------------------------------------------------------------------
__global__ __launch_bounds__(384) void k_qkv(
    const float* __restrict__ x,
    const float* __restrict__ Wq, const float* __restrict__ bq,
    const float* __restrict__ Wk, const float* __restrict__ bk,
    const float* __restrict__ Wv, const float* __restrict__ bv,
    float* __restrict__ q_out)
{
    __shared__ float sXh[64][40], sXl[64][40];
    const int tid  = threadIdx.x;
    const int lane = tid & 31, wid = tid >> 5;
    const int c4 = lane & 3, gid = lane >> 2;
    const int m_idx = wid >> 2;          // 0=q, 1=k, 2=v
    const int mtile = wid & 3;           // 16-row tile of W

    const int b  = blockIdx.x / 144;
    const int l0 = (blockIdx.x - b * 144) * 16;

    const float qscale = 0.35355339059327373f;  // 8^-0.5
    const float* Wm = (m_idx == 0) ? Wq : (m_idx == 1) ? Wk : Wv;
    const float* bm = (m_idx == 0) ? bq : (m_idx == 1) ? bk : bv;
    const float wsc = (m_idx == 0) ? qscale : 1.0f;

    const int row0 = mtile * 16 + gid;
    const int row1 = row0 + 8;

    // A-fragments for all 8 k-tiles (hi/lo)
    u32 wah[8][4], wal[8][4];
#pragma unroll
    for (int kt = 0; kt < 8; kt++) {
        const int k0 = kt * 8;
        float f0 = Wm[row0 * 64 + k0 + c4]     * wsc;
        float f1 = Wm[row1 * 64 + k0 + c4]     * wsc;
        float f2 = Wm[row0 * 64 + k0 + c4 + 4] * wsc;
        float f3 = Wm[row1 * 64 + k0 + c4 + 4] * wsc;
        CVT_TF32(wah[kt][0], f0); wal[kt][0] = __float_as_uint(f0 - __uint_as_float(wah[kt][0]));
        CVT_TF32(wah[kt][1], f1); wal[kt][1] = __float_as_uint(f1 - __uint_as_float(wah[kt][1]));
        CVT_TF32(wah[kt][2], f2); wal[kt][2] = __float_as_uint(f2 - __uint_as_float(wah[kt][2]));
        CVT_TF32(wah[kt][3], f3); wal[kt][3] = __float_as_uint(f3 - __uint_as_float(wah[kt][3]));
    }
    const float bz0 = bm[row0] * wsc;
    const float bz1 = bm[row1] * wsc;

    // Stage X tile hi/lo (64 ch x 16 cols)
    for (int i = tid; i < 1024; i += 384) {
        const int ch = i >> 4, c = i & 15;
        float f = x[((size_t)(b * 64 + ch)) * LL + l0 + c];
        u32 hb; CVT_TF32(hb, f);
        float hi = __uint_as_float(hb);
        sXh[ch][c] = hi;
        sXl[ch][c] = f - hi;
    }
    __syncthreads();

    float* dst = (m_idx == 0) ? g_q : (m_idx == 1) ? g_k : g_v;

#pragma unroll
    for (int nt = 0; nt < 2; nt++) {
        float gA0=0.f,gA1=0.f,gA2=0.f,gA3=0.f;   // Wh*Xh
        float gB0=0.f,gB1=0.f,gB2=0.f,gB3=0.f;   // cross terms
#pragma unroll
        for (int kt = 0; kt < 8; kt++) {
            const int kr = kt * 8;
            const u32 bh0 = __float_as_uint(sXh[kr + c4]    [nt * 8 + gid]);
            const u32 bh1 = __float_as_uint(sXh[kr + c4 + 4][nt * 8 + gid]);
            const u32 bl0 = __float_as_uint(sXl[kr + c4]    [nt * 8 + gid]);
            const u32 bl1 = __float_as_uint(sXl[kr + c4 + 4][nt * 8 + gid]);
            MMA_TF32(gA0,gA1,gA2,gA3, wah[kt][0],wah[kt][1],wah[kt][2],wah[kt][3], bh0,bh1);
            MMA_TF32(gB0,gB1,gB2,gB3, wah[kt][0],wah[kt][1],wah[kt][2],wah[kt][3], bl0,bl1);
            MMA_TF32(gB0,gB1,gB2,gB3, wal[kt][0],wal[kt][1],wal[kt][2],wal[kt][3], bh0,bh1);
        }
        const float c0 = gA0 + gB0 + bz0;
        const float c1 = gA1 + gB1 + bz0;
        const float c2 = gA2 + gB2 + bz1;
        const float c3 = gA3 + gB3 + bz1;

        const int n = l0 + nt * 8 + 2 * c4;
        const size_t i00 = ((size_t)(b * 64 + row0)) * LL + n;
        const size_t i10 = ((size_t)(b * 64 + row1)) * LL + n;
        if (m_idx == 0) {
            q_out[i00]     = c0;  q_out[i00 + 1] = c1;
            q_out[i10]     = c2;  q_out[i10 + 1] = c3;
            dst[i00]     = c0 * LOG2E;  dst[i00 + 1] = c1 * LOG2E;
            dst[i10]     = c2 * LOG2E;  dst[i10 + 1] = c3 * LOG2E;
        } else {
            dst[i00]     = c0;  dst[i00 + 1] = c1;
            dst[i10]     = c2;  dst[i10 + 1] = c3;
        }
    }
}

// ---------------------------------------------------------------------------
// K2 (pass A): tensor-core Z with split logit chains (proven R13).
// grid = (bh=16, kblk=18, qseg=2) x 256 thr.
// ---------------------------------------------------------------------------
__global__ __launch_bounds__(256) void k_passA()
{
    const int bh = blockIdx.x;
    const int b = bh >> 3, h = bh & 7;
    const size_t base = (size_t)(b * CH + h * DH) * LL;
    const int tid  = threadIdx.x;
    const int lane = tid & 31, wid = tid >> 5;
    const int c4 = lane & 3, gid = lane >> 2;
    const int wk = blockIdx.y * 128 + wid * 16;  // this warp's 16 k-cols
    const int qs = blockIdx.z;

    // Two fixed B-fragment groups (K hi/lo), cols [wk,wk+8) and [wk+8,wk+16)
    u32 bhA0, bhA1, blA0, blA1, bhB0, bhB1, blB0, blB1;
    {
        float f;
        f = g_k[base + (size_t)c4       * LL + wk + gid];
        CVT_TF32(bhA0, f); blA0 = __float_as_uint(f - __uint_as_float(bhA0));
        f = g_k[base + (size_t)(c4 + 4) * LL + wk + gid];
        CVT_TF32(bhA1, f); blA1 = __float_as_uint(f - __uint_as_float(bhA1));
        f = g_k[base + (size_t)c4       * LL + wk + 8 + gid];
        CVT_TF32(bhB0, f); blB0 = __float_as_uint(f - __uint_as_float(bhB0));
        f = g_k[base + (size_t)(c4 + 4) * LL + wk + 8 + gid];
        CVT_TF32(bhB1, f); blB1 = __float_as_uint(f - __uint_as_float(bhB1));
    }

    __shared__ float sqh[8][136], sql[8][136];

    float zA0 = 0.f, zA1 = 0.f, zB0 = 0.f, zB1 = 0.f;

    for (int chunk = 0; chunk < 9; chunk++) {
        const int q0 = qs * 1152 + chunk * 128;
        __syncthreads();
        for (int i = tid; i < 1024; i += 256) {
            const int d = i >> 7, qq = i & 127;
            float f = g_q[base + (size_t)d * LL + q0 + qq];
            u32 hb; CVT_TF32(hb, f);
            float hi = __uint_as_float(hb);
            sqh[d][qq] = hi;
            sql[d][qq] = f - hi;
        }
        __syncthreads();

#pragma unroll
        for (int qt = 0; qt < 8; qt++) {
            const int qq = qt * 16 + gid;
            const u32 ah0 = __float_as_uint(sqh[c4][qq]);
            const u32 ah1 = __float_as_uint(sqh[c4][qq + 8]);
            const u32 ah2 = __float_as_uint(sqh[c4 + 4][qq]);
            const u32 ah3 = __float_as_uint(sqh[c4 + 4][qq + 8]);
            const u32 al0 = __float_as_uint(sql[c4][qq]);
            const u32 al1 = __float_as_uint(sql[c4][qq + 8]);
            const u32 al2 = __float_as_uint(sql[c4 + 4][qq]);
            const u32 al3 = __float_as_uint(sql[c4 + 4][qq + 8]);

            float pAH0=0.f,pAH1=0.f,pAH2=0.f,pAH3=0.f;
            float pAL0=0.f,pAL1=0.f,pAL2=0.f,pAL3=0.f;
            float pBH0=0.f,pBH1=0.f,pBH2=0.f,pBH3=0.f;
            float pBL0=0.f,pBL1=0.f,pBL2=0.f,pBL3=0.f;
            MMA_TF32(pAH0,pAH1,pAH2,pAH3, ah0,ah1,ah2,ah3, bhA0,bhA1);
            MMA_TF32(pBH0,pBH1,pBH2,pBH3, ah0,ah1,ah2,ah3, bhB0,bhB1);
            MMA_TF32(pAL0,pAL1,pAL2,pAL3, ah0,ah1,ah2,ah3, blA0,blA1);
            MMA_TF32(pBL0,pBL1,pBL2,pBL3, ah0,ah1,ah2,ah3, blB0,blB1);
            MMA_TF32(pAL0,pAL1,pAL2,pAL3, al0,al1,al2,al3, bhA0,bhA1);
            MMA_TF32(pBL0,pBL1,pBL2,pBL3, al0,al1,al2,al3, bhB0,bhB1);

            float e0,e1,e2,e3,f0,f1,f2,f3;
            EX2F(e0, pAH0 + pAL0); EX2F(e1, pAH1 + pAL1);
            EX2F(e2, pAH2 + pAL2); EX2F(e3, pAH3 + pAL3);
            EX2F(f0, pBH0 + pBL0); EX2F(f1, pBH1 + pBL1);
            EX2F(f2, pBH2 + pBL2); EX2F(f3, pBH3 + pBL3);
            zA0 += e0 + e2;   // col wk + 2c4
            zA1 += e1 + e3;   // col wk + 2c4 + 1
            zB0 += f0 + f2;   // col wk + 8 + 2c4
            zB1 += f1 + f3;   // col wk + 8 + 2c4 + 1
        }
    }

    // reduce over the 8 gid-lanes sharing each column (lanes with same c4)
    zA0 += __shfl_xor_sync(0xffffffffu, zA0, 4);
    zA0 += __shfl_xor_sync(0xffffffffu, zA0, 8);
    zA0 += __shfl_xor_sync(0xffffffffu, zA0, 16);
    zA1 += __shfl_xor_sync(0xffffffffu, zA1, 4);
    zA1 += __shfl_xor_sync(0xffffffffu, zA1, 8);
    zA1 += __shfl_xor_sync(0xffffffffu, zA1, 16);
    zB0 += __shfl_xor_sync(0xffffffffu, zB0, 4);
    zB0 += __shfl_xor_sync(0xffffffffu, zB0, 8);
    zB0 += __shfl_xor_sync(0xffffffffu, zB0, 16);
    zB1 += __shfl_xor_sync(0xffffffffu, zB1, 4);
    zB1 += __shfl_xor_sync(0xffffffffu, zB1, 8);
    zB1 += __shfl_xor_sync(0xffffffffu, zB1, 16);

    if (lane < 4) {
        float* Zp = &g_Z[qs][bh][0];
        Zp[wk + 2 * lane]         = zA0;
        Zp[wk + 2 * lane + 1]     = zA1;
        Zp[wk + 8 + 2 * lane]     = zB0;
        Zp[wk + 8 + 2 * lane + 1] = zB1;
    }
}

// ---------------------------------------------------------------------------
// K3 (pass B): tensor-core, fused zinv, split chains, 4 AV accumulator
// groups (proven R13).  grid = (bh=16, qblk=18, kseg=2) x 256 thr.
// ---------------------------------------------------------------------------
__global__ __launch_bounds__(256) void k_passB()
{
    const int bh = blockIdx.x;
    const int b = bh >> 3, h = bh & 7;
    const size_t base = (size_t)(b * CH + h * DH) * LL;
    const int tid  = threadIdx.x;
    const int lane = tid & 31, wid = tid >> 5;
    const int c4 = lane & 3, gid = lane >> 2;
    const int q0 = blockIdx.y * 128 + wid * 16;
    const int kseg = blockIdx.z;

    // Q A-fragments (tf32 hi + f32 residual), rows=q, cols=d
    u32 ah[4], al[4];
    {
        float f0 = g_q[base + (size_t)c4 * LL + q0 + gid];
        float f1 = g_q[base + (size_t)c4 * LL + q0 + gid + 8];
        float f2 = g_q[base + (size_t)(c4 + 4) * LL + q0 + gid];
        float f3 = g_q[base + (size_t)(c4 + 4) * LL + q0 + gid + 8];
        CVT_TF32(ah[0], f0); al[0] = __float_as_uint(f0 - __uint_as_float(ah[0]));
        CVT_TF32(ah[1], f1); al[1] = __float_as_uint(f1 - __uint_as_float(ah[1]));
        CVT_TF32(ah[2], f2); al[2] = __float_as_uint(f2 - __uint_as_float(ah[2]));
        CVT_TF32(ah[3], f3); al[3] = __float_as_uint(f3 - __uint_as_float(ah[3]));
    }

    __shared__ float  skhi[8][136], sklo[8][136];
    __shared__ __half svh [8][136], svl [8][136];

    const int fkk = tid & 127;      // fixed k column this thread fills
    const int fd0 = tid >> 7;       // starting row (0/1), step 2

    // 4 independent accumulator groups
    float oA0=0.f,oA1=0.f,oA2=0.f,oA3=0.f;   // vh, even kt
    float oB0=0.f,oB1=0.f,oB2=0.f,oB3=0.f;   // vl, even kt
    float oC0=0.f,oC1=0.f,oC2=0.f,oC3=0.f;   // vh, odd kt
    float oD0=0.f,oD1=0.f,oD2=0.f,oD3=0.f;   // vl, odd kt

    for (int chunk = 0; chunk < 9; chunk++) {
        const int kc = kseg * 1152 + chunk * 128;
        __syncthreads();
        {
            const float zi = 1.0f / (g_Z[0][bh][kc + fkk] + g_Z[1][bh][kc + fkk]);
#pragma unroll
            for (int j = 0; j < 4; j++) {
                const int d = fd0 + 2 * j;
                float kvf = g_k[base + (size_t)d * LL + kc + fkk];
                u32 hb; CVT_TF32(hb, kvf);
                float hi = __uint_as_float(hb);
                skhi[d][fkk] = hi;
                sklo[d][fkk] = kvf - hi;
                float vv = g_v[base + (size_t)d * LL + kc + fkk] * zi;
                __half vh = __float2half_rn(vv);
                svh[d][fkk] = vh;
                svl[d][fkk] = __float2half_rn(vv - __half2float(vh));
            }
        }
        __syncthreads();

#pragma unroll
        for (int kt = 0; kt < 8; kt++) {
            const int kx0 = kt * 16 + gid;
            const int kx1 = kx0 + 8;
            const u32 b00 = __float_as_uint(skhi[c4][kx0]);
            const u32 b01 = __float_as_uint(skhi[c4 + 4][kx0]);
            const u32 l00 = __float_as_uint(sklo[c4][kx0]);
            const u32 l01 = __float_as_uint(sklo[c4 + 4][kx0]);
            const u32 b10 = __float_as_uint(skhi[c4][kx1]);
            const u32 b11 = __float_as_uint(skhi[c4 + 4][kx1]);
            const u32 l10 = __float_as_uint(sklo[c4][kx1]);
            const u32 l11 = __float_as_uint(sklo[c4 + 4][kx1]);

            float pH0=0.f,pH1=0.f,pH2=0.f,pH3=0.f;
            float pL0=0.f,pL1=0.f,pL2=0.f,pL3=0.f;
            float rH0=0.f,rH1=0.f,rH2=0.f,rH3=0.f;
            float rL0=0.f,rL1=0.f,rL2=0.f,rL3=0.f;
            MMA_TF32(pH0,pH1,pH2,pH3, ah[0],ah[1],ah[2],ah[3], b00,b01);
            MMA_TF32(rH0,rH1,rH2,rH3, ah[0],ah[1],ah[2],ah[3], b10,b11);
            MMA_TF32(pL0,pL1,pL2,pL3, ah[0],ah[1],ah[2],ah[3], l00,l01);
            MMA_TF32(rL0,rL1,rL2,rL3, ah[0],ah[1],ah[2],ah[3], l10,l11);
            MMA_TF32(pL0,pL1,pL2,pL3, al[0],al[1],al[2],al[3], b00,b01);
            MMA_TF32(rL0,rL1,rL2,rL3, al[0],al[1],al[2],al[3], b10,b11);

            float e0,e1,e2,e3,f0,f1,f2,f3;
            EX2F(e0, pH0 + pL0); EX2F(e1, pH1 + pL1);
            EX2F(e2, pH2 + pL2); EX2F(e3, pH3 + pL3);
            EX2F(f0, rH0 + rL0); EX2F(f1, rH1 + rL1);
            EX2F(f2, rH2 + rL2); EX2F(f3, rH3 + rL3);

            u32 wh0, wh1, wh2, wh3;
            PACK_F16X2(wh0, e1, e0);
            PACK_F16X2(wh1, e3, e2);
            PACK_F16X2(wh2, f1, f0);
            PACK_F16X2(wh3, f3, f2);

            const u32 vh0 = *reinterpret_cast<const u32*>(&svh[gid][kt * 16 + 2 * c4]);
            const u32 vh1 = *reinterpret_cast<const u32*>(&svh[gid][kt * 16 + 2 * c4 + 8]);
            const u32 vl0 = *reinterpret_cast<const u32*>(&svl[gid][kt * 16 + 2 * c4]);
            const u32 vl1 = *reinterpret_cast<const u32*>(&svl[gid][kt * 16 + 2 * c4 + 8]);

            if (kt & 1) {
                MMA_F16(oC0,oC1,oC2,oC3, wh0,wh1,wh2,wh3, vh0,vh1);
                MMA_F16(oD0,oD1,oD2,oD3, wh0,wh1,wh2,wh3, vl0,vl1);
            } else {
                MMA_F16(oA0,oA1,oA2,oA3, wh0,wh1,wh2,wh3, vh0,vh1);
                MMA_F16(oB0,oB1,oB2,oB3, wh0,wh1,wh2,wh3, vl0,vl1);
            }
        }
    }

    const float oc0 = (oA0 + oB0) + (oC0 + oD0);
    const float oc1 = (oA1 + oB1) + (oC1 + oD1);
    const float oc2 = (oA2 + oB2) + (oC2 + oD2);
    const float oc3 = (oA3 + oB3) + (oC3 + oD3);

    float* Ob = g_op[kseg] + base;
    Ob[(size_t)(2 * c4)     * LL + q0 + gid]     = oc0;
    Ob[(size_t)(2 * c4 + 1) * LL + q0 + gid]     = oc1;
    Ob[(size_t)(2 * c4)     * LL + q0 + gid + 8] = oc2;
    Ob[(size_t)(2 * c4 + 1) * LL + q0 + gid + 8] = oc3;
}

// ---------------------------------------------------------------------------
// K4: output 1x1 conv as tf32 tensor GEMM with fused 2-partial reduction.
// grid = 288 x 256 (8 warps; 16 cols per block; warp = mtile x n-tile).
// ---------------------------------------------------------------------------
__global__ __launch_bounds__(256) void k_oconv(
    const float* __restrict__ Wo, const float* __restrict__ bo,
    float* __restrict__ out)
{
    __shared__ float sXh[64][40], sXl[64][40];
    const int tid  = threadIdx.x;
    const int lane = tid & 31, wid = tid >> 5;
    const int c4 = lane & 3, gid = lane >> 2;
    const int mtile = wid & 3;
    const int nt    = wid >> 2;          // 0/1: which 8-col tile

    const int b  = blockIdx.x / 144;
    const int l0 = (blockIdx.x - b * 144) * 16;

    const int row0 = mtile * 16 + gid;
    const int row1 = row0 + 8;

    // A-fragments for all 8 k-tiles (hi/lo)
    u32 wah[8][4], wal[8][4];
#pragma unroll
    for (int kt = 0; kt < 8; kt++) {
        const int k0 = kt * 8;
        float f0 = Wo[row0 * 64 + k0 + c4];
        float f1 = Wo[row1 * 64 + k0 + c4];
        float f2 = Wo[row0 * 64 + k0 + c4 + 4];
        float f3 = Wo[row1 * 64 + k0 + c4 + 4];
        CVT_TF32(wah[kt][0], f0); wal[kt][0] = __float_as_uint(f0 - __uint_as_float(wah[kt][0]));
        CVT_TF32(wah[kt][1], f1); wal[kt][1] = __float_as_uint(f1 - __uint_as_float(wah[kt][1]));
        CVT_TF32(wah[kt][2], f2); wal[kt][2] = __float_as_uint(f2 - __uint_as_float(wah[kt][2]));
        CVT_TF32(wah[kt][3], f3); wal[kt][3] = __float_as_uint(f3 - __uint_as_float(wah[kt][3]));
    }
    const float bz0 = bo[row0];
    const float bz1 = bo[row1];

    // Stage X = op0 + op1 tile hi/lo (64 ch x 16 cols)
    for (int i = tid; i < 1024; i += 256) {
        const int ch = i >> 4, c = i & 15;
        const size_t idx = ((size_t)(b * 64 + ch)) * LL + l0 + c;
        float f = g_op[0][idx] + g_op[1][idx];
        u32 hb; CVT_TF32(hb, f);
        float hi = __uint_as_float(hb);
        sXh[ch][c] = hi;
        sXl[ch][c] = f - hi;
    }
    __syncthreads();

    float gA0=0.f,gA1=0.f,gA2=0.f,gA3=0.f;
    float gB0=0.f,gB1=0.f,gB2=0.f,gB3=0.f;
#pragma unroll
    for (int kt = 0; kt < 8; kt++) {
        const int kr = kt * 8;
        const u32 bh0 = __float_as_uint(sXh[kr + c4]    [nt * 8 + gid]);
        const u32 bh1 = __float_as_uint(sXh[kr + c4 + 4][nt * 8 + gid]);
        const u32 bl0 = __float_as_uint(sXl[kr + c4]    [nt * 8 + gid]);
        const u32 bl1 = __float_as_uint(sXl[kr + c4 + 4][nt * 8 + gid]);
        MMA_TF32(gA0,gA1,gA2,gA3, wah[kt][0],wah[kt][1],wah[kt][2],wah[kt][3], bh0,bh1);
        MMA_TF32(gB0,gB1,gB2,gB3, wah[kt][0],wah[kt][1],wah[kt][2],wah[kt][3], bl0,bl1);
        MMA_TF32(gB0,gB1,gB2,gB3, wal[kt][0],wal[kt][1],wal[kt][2],wal[kt][3], bh0,bh1);
    }
    const int n = l0 + nt * 8 + 2 * c4;
    const size_t i00 = ((size_t)(b * 64 + row0)) * LL + n;
    const size_t i10 = ((size_t)(b * 64 + row1)) * LL + n;
    out[i00]     = gA0 + gB0 + bz0;
    out[i00 + 1] = gA1 + gB1 + bz0;
    out[i10]     = gA2 + gB2 + bz1;
    out[i10 + 1] = gA3 + gB3 + bz1;
}

// ---------------------------------------------------------------------------
extern "C" void kernel_launch(void* const* d_in, const int* in_sizes, int n_in,
                              void* d_out, int out_size)
{
    const float* x  = (const float*)d_in[0];
    const float* Wq = (const float*)d_in[1];
    const float* bq = (const float*)d_in[2];
    const float* Wk = (const float*)d_in[3];
    const float* bk = (const float*)d_in[4];
    const float* Wv = (const float*)d_in[5];
    const float* bv = (const float*)d_in[6];
    const float* Wo = (const float*)d_in[7];
    const float* bo = (const float*)d_in[8];

    float* out   = (float*)d_out;           // first output: conv result
    float* q_out = (float*)d_out + BCHL;    // second output: scaled q

    k_qkv<<<288, 384>>>(x, Wq, bq, Wk, bk, Wv, bv, q_out);
    k_passA<<<dim3(16, 18, 2), 256>>>();
    k_passB<<<dim3(16, 18, 2), 256>>>();
    k_oconv<<<288, 256>>>(Wo, bo, out);
}

// round 16
// speedup vs baseline: 1.0418x; 1.0418x over previous
#include <cuda_runtime.h>
#include <cuda_fp16.h>

// Problem constants (fixed by the reference setup)
#define BB   2
#define CH   64
#define NH   8
#define DH   8
#define HW   48
#define LL   2304            // HW*HW
#define BCHL (BB*CH*LL)      // 294912

#define LOG2E 1.4426950408889634f

#define EX2F(r,x)     asm("ex2.approx.ftz.f32 %0,%1;"  : "=f"(r) : "f"(x))
#define CVT_TF32(u,x) asm("cvt.rna.tf32.f32 %0,%1;"    : "=r"(u) : "f"(x))
// d = {hi=cvt(a), lo=cvt(b)}
#define PACK_F16X2(d,a,b) asm("cvt.rn.f16x2.f32 %0,%1,%2;" : "=r"(d) : "f"(a), "f"(b))

#define MMA_TF32(d0,d1,d2,d3,a0,a1,a2,a3,b0,b1) \
  asm volatile("mma.sync.aligned.m16n8k8.row.col.f32.tf32.tf32.f32 " \
    "{%0,%1,%2,%3},{%4,%5,%6,%7},{%8,%9},{%0,%1,%2,%3};" \
    : "+f"(d0),"+f"(d1),"+f"(d2),"+f"(d3) \
    : "r"(a0),"r"(a1),"r"(a2),"r"(a3),"r"(b0),"r"(b1))

#define MMA_F16(d0,d1,d2,d3,a0,a1,a2,a3,b0,b1) \
  asm volatile("mma.sync.aligned.m16n8k16.row.col.f32.f16.f16.f32 " \
    "{%0,%1,%2,%3},{%4,%5,%6,%7},{%8,%9},{%0,%1,%2,%3};" \
    : "+f"(d0),"+f"(d1),"+f"(d2),"+f"(d3) \
    : "r"(a0),"r"(a1),"r"(a2),"r"(a3),"r"(b0),"r"(b1))

typedef unsigned int u32;

// Scratch (device globals — no allocation allowed)
__device__ float g_q [BCHL];          // q * d^-0.5 * log2(e)  (for EX2)
__device__ float g_k [BCHL];
__device__ float g_v [BCHL];
__device__ float g_Z [2][BB*NH][LL];  // 2 q-split partials
__device__ float g_op[2][BCHL];

// ---------------------------------------------------------------------------
// K1: q/k/v 1x1 convs as tf32 tensor GEMM.  grid = 144 x 384 (12 warps),
// 32 cols/block (W-fragment loads amortized over a wider tile).
// Warp (m_idx = wid>>2 in {q,k,v}, mtile = wid&3); pad 40 = conflict-free.
// ---------------------------------------------------------------------------
__global__ __launch_bounds__(384) void k_qkv(
    const float* __restrict__ x,
    const float* __restrict__ Wq, const float* __restrict__ bq,
    const float* __restrict__ Wk, const float* __restrict__ bk,
    const float* __restrict__ Wv, const float* __restrict__ bv,
    float* __restrict__ q_out)
{
    __shared__ float sXh[64][40], sXl[64][40];
    const int tid  = threadIdx.x;
    const int lane = tid & 31, wid = tid >> 5;
    const int c4 = lane & 3, gid = lane >> 2;
    const int m_idx = wid >> 2;          // 0=q, 1=k, 2=v
    const int mtile = wid & 3;           // 16-row tile of W

    const int b  = blockIdx.x / 72;
    const int l0 = (blockIdx.x - b * 72) * 32;

    const float qscale = 0.35355339059327373f;  // 8^-0.5
    const float* Wm = (m_idx == 0) ? Wq : (m_idx == 1) ? Wk : Wv;
    const float* bm = (m_idx == 0) ? bq : (m_idx == 1) ? bk : bv;
    const float wsc = (m_idx == 0) ? qscale : 1.0f;

    const int row0 = mtile * 16 + gid;
    const int row1 = row0 + 8;

    // A-fragments for all 8 k-tiles (hi/lo)
    u32 wah[8][4], wal[8][4];
#pragma unroll
    for (int kt = 0; kt < 8; kt++) {
        const int k0 = kt * 8;
        float f0 = Wm[row0 * 64 + k0 + c4]     * wsc;
        float f1 = Wm[row1 * 64 + k0 + c4]     * wsc;
        float f2 = Wm[row0 * 64 + k0 + c4 + 4] * wsc;
        float f3 = Wm[row1 * 64 + k0 + c4 + 4] * wsc;
        CVT_TF32(wah[kt][0], f0); wal[kt][0] = __float_as_uint(f0 - __uint_as_float(wah[kt][0]));
        CVT_TF32(wah[kt][1], f1); wal[kt][1] = __float_as_uint(f1 - __uint_as_float(wah[kt][1]));
        CVT_TF32(wah[kt][2], f2); wal[kt][2] = __float_as_uint(f2 - __uint_as_float(wah[kt][2]));
        CVT_TF32(wah[kt][3], f3); wal[kt][3] = __float_as_uint(f3 - __uint_as_float(wah[kt][3]));
    }
    const float bz0 = bm[row0] * wsc;
    const float bz1 = bm[row1] * wsc;

    // Stage X tile hi/lo (64 ch x 32 cols)
    for (int i = tid; i < 2048; i += 384) {
        const int ch = i >> 5, c = i & 31;
        float f = x[((size_t)(b * 64 + ch)) * LL + l0 + c];
        u32 hb; CVT_TF32(hb, f);
        float hi = __uint_as_float(hb);
        sXh[ch][c] = hi;
        sXl[ch][c] = f - hi;
    }
    __syncthreads();

    float* dst = (m_idx == 0) ? g_q : (m_idx == 1) ? g_k : g_v;

#pragma unroll
    for (int nt = 0; nt < 4; nt++) {
        float gA0=0.f,gA1=0.f,gA2=0.f,gA3=0.f;   // Wh*Xh
        float gB0=0.f,gB1=0.f,gB2=0.f,gB3=0.f;   // cross terms
#pragma unroll
        for (int kt = 0; kt < 8; kt++) {
            const int kr = kt * 8;
            const u32 bh0 = __float_as_uint(sXh[kr + c4]    [nt * 8 + gid]);
            const u32 bh1 = __float_as_uint(sXh[kr + c4 + 4][nt * 8 + gid]);
            const u32 bl0 = __float_as_uint(sXl[kr + c4]    [nt * 8 + gid]);
            const u32 bl1 = __float_as_uint(sXl[kr + c4 + 4][nt * 8 + gid]);
            MMA_TF32(gA0,gA1,gA2,gA3, wah[kt][0],wah[kt][1],wah[kt][2],wah[kt][3], bh0,bh1);
            MMA_TF32(gB0,gB1,gB2,gB3, wah[kt][0],wah[kt][1],wah[kt][2],wah[kt][3], bl0,bl1);
            MMA_TF32(gB0,gB1,gB2,gB3, wal[kt][0],wal[kt][1],wal[kt][2],wal[kt][3], bh0,bh1);
        }
        const float c0 = gA0 + gB0 + bz0;
        const float c1 = gA1 + gB1 + bz0;
        const float c2 = gA2 + gB2 + bz1;
        const float c3 = gA3 + gB3 + bz1;

        const int n = l0 + nt * 8 + 2 * c4;
        const size_t i00 = ((size_t)(b * 64 + row0)) * LL + n;
        const size_t i10 = ((size_t)(b * 64 + row1)) * LL + n;
        if (m_idx == 0) {
            q_out[i00]     = c0;  q_out[i00 + 1] = c1;
            q_out[i10]     = c2;  q_out[i10 + 1] = c3;
            dst[i00]     = c0 * LOG2E;  dst[i00 + 1] = c1 * LOG2E;
            dst[i10]     = c2 * LOG2E;  dst[i10 + 1] = c3 * LOG2E;
        } else {
            dst[i00]     = c0;  dst[i00 + 1] = c1;
            dst[i10]     = c2;  dst[i10 + 1] = c3;
        }
    }
}

// ---------------------------------------------------------------------------
// K2 (pass A): tensor-core Z with split logit chains (proven R13).
// grid = (bh=16, kblk=18, qseg=2) x 256 thr.
// ---------------------------------------------------------------------------
__global__ __launch_bounds__(256) void k_passA()
{
    const int bh = blockIdx.x;
    const int b = bh >> 3, h = bh & 7;
    const size_t base = (size_t)(b * CH + h * DH) * LL;
    const int tid  = threadIdx.x;
    const int lane = tid & 31, wid = tid >> 5;
    const int c4 = lane & 3, gid = lane >> 2;
    const int wk = blockIdx.y * 128 + wid * 16;  // this warp's 16 k-cols
    const int qs = blockIdx.z;

    // Two fixed B-fragment groups (K hi/lo), cols [wk,wk+8) and [wk+8,wk+16)
    u32 bhA0, bhA1, blA0, blA1, bhB0, bhB1, blB0, blB1;
    {
        float f;
        f = g_k[base + (size_t)c4       * LL + wk + gid];
        CVT_TF32(bhA0, f); blA0 = __float_as_uint(f - __uint_as_float(bhA0));
        f = g_k[base + (size_t)(c4 + 4) * LL + wk + gid];
        CVT_TF32(bhA1, f); blA1 = __float_as_uint(f - __uint_as_float(bhA1));
        f = g_k[base + (size_t)c4       * LL + wk + 8 + gid];
        CVT_TF32(bhB0, f); blB0 = __float_as_uint(f - __uint_as_float(bhB0));
        f = g_k[base + (size_t)(c4 + 4) * LL + wk + 8 + gid];
        CVT_TF32(bhB1, f); blB1 = __float_as_uint(f - __uint_as_float(bhB1));
    }

    __shared__ float sqh[8][136], sql[8][136];

    float zA0 = 0.f, zA1 = 0.f, zB0 = 0.f, zB1 = 0.f;

    for (int chunk = 0; chunk < 9; chunk++) {
        const int q0 = qs * 1152 + chunk * 128;
        __syncthreads();
        for (int i = tid; i < 1024; i += 256) {
            const int d = i >> 7, qq = i & 127;
            float f = g_q[base + (size_t)d * LL + q0 + qq];
            u32 hb; CVT_TF32(hb, f);
            float hi = __uint_as_float(hb);
            sqh[d][qq] = hi;
            sql[d][qq] = f - hi;
        }
        __syncthreads();

#pragma unroll
        for (int qt = 0; qt < 8; qt++) {
            const int qq = qt * 16 + gid;
            const u32 ah0 = __float_as_uint(sqh[c4][qq]);
            const u32 ah1 = __float_as_uint(sqh[c4][qq + 8]);
            const u32 ah2 = __float_as_uint(sqh[c4 + 4][qq]);
            const u32 ah3 = __float_as_uint(sqh[c4 + 4][qq + 8]);
            const u32 al0 = __float_as_uint(sql[c4][qq]);
            const u32 al1 = __float_as_uint(sql[c4][qq + 8]);
            const u32 al2 = __float_as_uint(sql[c4 + 4][qq]);
            const u32 al3 = __float_as_uint(sql[c4 + 4][qq + 8]);

            float pAH0=0.f,pAH1=0.f,pAH2=0.f,pAH3=0.f;
            float pAL0=0.f,pAL1=0.f,pAL2=0.f,pAL3=0.f;
            float pBH0=0.f,pBH1=0.f,pBH2=0.f,pBH3=0.f;
            float pBL0=0.f,pBL1=0.f,pBL2=0.f,pBL3=0.f;
            MMA_TF32(pAH0,pAH1,pAH2,pAH3, ah0,ah1,ah2,ah3, bhA0,bhA1);
            MMA_TF32(pBH0,pBH1,pBH2,pBH3, ah0,ah1,ah2,ah3, bhB0,bhB1);
            MMA_TF32(pAL0,pAL1,pAL2,pAL3, ah0,ah1,ah2,ah3, blA0,blA1);
            MMA_TF32(pBL0,pBL1,pBL2,pBL3, ah0,ah1,ah2,ah3, blB0,blB1);
            MMA_TF32(pAL0,pAL1,pAL2,pAL3, al0,al1,al2,al3, bhA0,bhA1);
            MMA_TF32(pBL0,pBL1,pBL2,pBL3, al0,al1,al2,al3, bhB0,bhB1);

            float e0,e1,e2,e3,f0,f1,f2,f3;
            EX2F(e0, pAH0 + pAL0); EX2F(e1, pAH1 + pAL1);
            EX2F(e2, pAH2 + pAL2); EX2F(e3, pAH3 + pAL3);
            EX2F(f0, pBH0 + pBL0); EX2F(f1, pBH1 + pBL1);
            EX2F(f2, pBH2 + pBL2); EX2F(f3, pBH3 + pBL3);
            zA0 += e0 + e2;   // col wk + 2c4
            zA1 += e1 + e3;   // col wk + 2c4 + 1
            zB0 += f0 + f2;   // col wk + 8 + 2c4
            zB1 += f1 + f3;   // col wk + 8 + 2c4 + 1
        }
    }

    // reduce over the 8 gid-lanes sharing each column (lanes with same c4)
    zA0 += __shfl_xor_sync(0xffffffffu, zA0, 4);
    zA0 += __shfl_xor_sync(0xffffffffu, zA0, 8);
    zA0 += __shfl_xor_sync(0xffffffffu, zA0, 16);
    zA1 += __shfl_xor_sync(0xffffffffu, zA1, 4);
    zA1 += __shfl_xor_sync(0xffffffffu, zA1, 8);
    zA1 += __shfl_xor_sync(0xffffffffu, zA1, 16);
    zB0 += __shfl_xor_sync(0xffffffffu, zB0, 4);
    zB0 += __shfl_xor_sync(0xffffffffu, zB0, 8);
    zB0 += __shfl_xor_sync(0xffffffffu, zB0, 16);
    zB1 += __shfl_xor_sync(0xffffffffu, zB1, 4);
    zB1 += __shfl_xor_sync(0xffffffffu, zB1, 8);
    zB1 += __shfl_xor_sync(0xffffffffu, zB1, 16);

    if (lane < 4) {
        float* Zp = &g_Z[qs][bh][0];
        Zp[wk + 2 * lane]         = zA0;
        Zp[wk + 2 * lane + 1]     = zA1;
        Zp[wk + 8 + 2 * lane]     = zB0;
        Zp[wk + 8 + 2 * lane + 1] = zB1;
    }
}

// ---------------------------------------------------------------------------
// K3 (pass B): tensor-core, fused zinv, split chains, 4 AV accumulator
// groups + DOUBLE-BUFFERED SMEM pipeline (register prefetch of chunk+1's
// global loads under chunk's compute; one sync per iteration).
// grid = (bh=16, qblk=18, kseg=2) x 256 thr.
// ---------------------------------------------------------------------------
__global__ __launch_bounds__(256) void k_passB()
{
    const int bh = blockIdx.x;
    const int b = bh >> 3, h = bh & 7;
    const size_t base = (size_t)(b * CH + h * DH) * LL;
    const int tid  = threadIdx.x;
    const int lane = tid & 31, wid = tid >> 5;
    const int c4 = lane & 3, gid = lane >> 2;
    const int q0 = blockIdx.y * 128 + wid * 16;
    const int kseg = blockIdx.z;

    // Q A-fragments (tf32 hi + f32 residual), rows=q, cols=d
    u32 ah[4], al[4];
    {
        float f0 = g_q[base + (size_t)c4 * LL + q0 + gid];
        float f1 = g_q[base + (size_t)c4 * LL + q0 + gid + 8];
        float f2 = g_q[base + (size_t)(c4 + 4) * LL + q0 + gid];
        float f3 = g_q[base + (size_t)(c4 + 4) * LL + q0 + gid + 8];
        CVT_TF32(ah[0], f0); al[0] = __float_as_uint(f0 - __uint_as_float(ah[0]));
        CVT_TF32(ah[1], f1); al[1] = __float_as_uint(f1 - __uint_as_float(ah[1]));
        CVT_TF32(ah[2], f2); al[2] = __float_as_uint(f2 - __uint_as_float(ah[2]));
        CVT_TF32(ah[3], f3); al[3] = __float_as_uint(f3 - __uint_as_float(ah[3]));
    }

    __shared__ float  skhi[2][8][136], sklo[2][8][136];
    __shared__ __half svh [2][8][136], svl [2][8][136];

    const int fkk = tid & 127;      // fixed k column this thread fills
    const int fd0 = tid >> 7;       // starting row (0/1), step 2

    // prefetch registers
    float pzA, pzB, pk[4], pv[4];

    // load + store chunk 0 into buffer 0
    {
        const int kc = kseg * 1152;
        pzA = g_Z[0][bh][kc + fkk];
        pzB = g_Z[1][bh][kc + fkk];
#pragma unroll
        for (int j = 0; j < 4; j++) {
            const int d = fd0 + 2 * j;
            pk[j] = g_k[base + (size_t)d * LL + kc + fkk];
            pv[j] = g_v[base + (size_t)d * LL + kc + fkk];
        }
        const float zi = 1.0f / (pzA + pzB);
#pragma unroll
        for (int j = 0; j < 4; j++) {
            const int d = fd0 + 2 * j;
            u32 hb; CVT_TF32(hb, pk[j]);
            float hi = __uint_as_float(hb);
            skhi[0][d][fkk] = hi;
            sklo[0][d][fkk] = pk[j] - hi;
            float vv = pv[j] * zi;
            __half vh_ = __float2half_rn(vv);
            svh[0][d][fkk] = vh_;
            svl[0][d][fkk] = __float2half_rn(vv - __half2float(vh_));
        }
    }
    __syncthreads();

    // 4 independent accumulator groups
    float oA0=0.f,oA1=0.f,oA2=0.f,oA3=0.f;   // vh, even kt
    float oB0=0.f,oB1=0.f,oB2=0.f,oB3=0.f;   // vl, even kt
    float oC0=0.f,oC1=0.f,oC2=0.f,oC3=0.f;   // vh, odd kt
    float oD0=0.f,oD1=0.f,oD2=0.f,oD3=0.f;   // vl, odd kt

    for (int chunk = 0; chunk < 9; chunk++) {
        const int cur = chunk & 1;

        // prefetch next chunk's globals (latency hidden under compute)
        if (chunk < 8) {
            const int kc = kseg * 1152 + (chunk + 1) * 128;
            pzA = g_Z[0][bh][kc + fkk];
            pzB = g_Z[1][bh][kc + fkk];
#pragma unroll
            for (int j = 0; j < 4; j++) {
                const int d = fd0 + 2 * j;
                pk[j] = g_k[base + (size_t)d * LL + kc + fkk];
                pv[j] = g_v[base + (size_t)d * LL + kc + fkk];
            }
        }

#pragma unroll
        for (int kt = 0; kt < 8; kt++) {
            const int kx0 = kt * 16 + gid;
            const int kx1 = kx0 + 8;
            const u32 b00 = __float_as_uint(skhi[cur][c4][kx0]);
            const u32 b01 = __float_as_uint(skhi[cur][c4 + 4][kx0]);
            const u32 l00 = __float_as_uint(sklo[cur][c4][kx0]);
            const u32 l01 = __float_as_uint(sklo[cur][c4 + 4][kx0]);
            const u32 b10 = __float_as_uint(skhi[cur][c4][kx1]);
            const u32 b11 = __float_as_uint(skhi[cur][c4 + 4][kx1]);
            const u32 l10 = __float_as_uint(sklo[cur][c4][kx1]);
            const u32 l11 = __float_as_uint(sklo[cur][c4 + 4][kx1]);

            float pH0=0.f,pH1=0.f,pH2=0.f,pH3=0.f;
            float pL0=0.f,pL1=0.f,pL2=0.f,pL3=0.f;
            float rH0=0.f,rH1=0.f,rH2=0.f,rH3=0.f;
            float rL0=0.f,rL1=0.f,rL2=0.f,rL3=0.f;
            MMA_TF32(pH0,pH1,pH2,pH3, ah[0],ah[1],ah[2],ah[3], b00,b01);
            MMA_TF32(rH0,rH1,rH2,rH3, ah[0],ah[1],ah[2],ah[3], b10,b11);
            MMA_TF32(pL0,pL1,pL2,pL3, ah[0],ah[1],ah[2],ah[3], l00,l01);
            MMA_TF32(rL0,rL1,rL2,rL3, ah[0],ah[1],ah[2],ah[3], l10,l11);
            MMA_TF32(pL0,pL1,pL2,pL3, al[0],al[1],al[2],al[3], b00,b01);
            MMA_TF32(rL0,rL1,rL2,rL3, al[0],al[1],al[2],al[3], b10,b11);

            float e0,e1,e2,e3,f0,f1,f2,f3;
            EX2F(e0, pH0 + pL0); EX2F(e1, pH1 + pL1);
            EX2F(e2, pH2 + pL2); EX2F(e3, pH3 + pL3);
            EX2F(f0, rH0 + rL0); EX2F(f1, rH1 + rL1);
            EX2F(f2, rH2 + rL2); EX2F(f3, rH3 + rL3);

            u32 wh0, wh1, wh2, wh3;
            PACK_F16X2(wh0, e1, e0);
            PACK_F16X2(wh1, e3, e2);
            PACK_F16X2(wh2, f1, f0);
            PACK_F16X2(wh3, f3, f2);

            const u32 vh0 = *reinterpret_cast<const u32*>(&svh[cur][gid][kt * 16 + 2 * c4]);
            const u32 vh1 = *reinterpret_cast<const u32*>(&svh[cur][gid][kt * 16 + 2 * c4 + 8]);
            const u32 vl0 = *reinterpret_cast<const u32*>(&svl[cur][gid][kt * 16 + 2 * c4]);
            const u32 vl1 = *reinterpret_cast<const u32*>(&svl[cur][gid][kt * 16 + 2 * c4 + 8]);

            if (kt & 1) {
                MMA_F16(oC0,oC1,oC2,oC3, wh0,wh1,wh2,wh3, vh0,vh1);
                MMA_F16(oD0,oD1,oD2,oD3, wh0,wh1,wh2,wh3, vl0,vl1);
            } else {
                MMA_F16(oA0,oA1,oA2,oA3, wh0,wh1,wh2,wh3, vh0,vh1);
                MMA_F16(oB0,oB1,oB2,oB3, wh0,wh1,wh2,wh3, vl0,vl1);
            }
        }

        // store prefetched chunk into the other buffer, then one sync
        if (chunk < 8) {
            const int nb = cur ^ 1;
            const float zi = 1.0f / (pzA + pzB);
#pragma unroll
            for (int j = 0; j < 4; j++) {
                const int d = fd0 + 2 * j;
                u32 hb; CVT_TF32(hb, pk[j]);
                float hi = __uint_as_float(hb);
                skhi[nb][d][fkk] = hi;
                sklo[nb][d][fkk] = pk[j] - hi;
                float vv = pv[j] * zi;
                __half vh_ = __float2half_rn(vv);
                svh[nb][d][fkk] = vh_;
                svl[nb][d][fkk] = __float2half_rn(vv - __half2float(vh_));
            }
            __syncthreads();
        }
    }

    const float oc0 = (oA0 + oB0) + (oC0 + oD0);
    const float oc1 = (oA1 + oB1) + (oC1 + oD1);
    const float oc2 = (oA2 + oB2) + (oC2 + oD2);
    const float oc3 = (oA3 + oB3) + (oC3 + oD3);

    float* Ob = g_op[kseg] + base;
    Ob[(size_t)(2 * c4)     * LL + q0 + gid]     = oc0;
    Ob[(size_t)(2 * c4 + 1) * LL + q0 + gid]     = oc1;
    Ob[(size_t)(2 * c4)     * LL + q0 + gid + 8] = oc2;
    Ob[(size_t)(2 * c4 + 1) * LL + q0 + gid + 8] = oc3;
}

// ---------------------------------------------------------------------------
// K4: output 1x1 conv as tf32 tensor GEMM with fused 2-partial reduction.
// grid = 288 x 256 (8 warps; 16 cols per block; warp = mtile x n-tile).
// ---------------------------------------------------------------------------
__global__ __launch_bounds__(256) void k_oconv(
    const float* __restrict__ Wo, const float* __restrict__ bo,
    float* __restrict__ out)
{
    __shared__ float sXh[64][40], sXl[64][40];
    const int tid  = threadIdx.x;
    const int lane = tid & 31, wid = tid >> 5;
    const int c4 = lane & 3, gid = lane >> 2;
    const int mtile = wid & 3;
    const int nt    = wid >> 2;          // 0/1: which 8-col tile

    const int b  = blockIdx.x / 144;
    const int l0 = (blockIdx.x - b * 144) * 16;

    const int row0 = mtile * 16 + gid;
    const int row1 = row0 + 8;

    // A-fragments for all 8 k-tiles (hi/lo)
    u32 wah[8][4], wal[8][4];
#pragma unroll
    for (int kt = 0; kt < 8; kt++) {
        const int k0 = kt * 8;
        float f0 = Wo[row0 * 64 + k0 + c4];
        float f1 = Wo[row1 * 64 + k0 + c4];
        float f2 = Wo[row0 * 64 + k0 + c4 + 4];
        float f3 = Wo[row1 * 64 + k0 + c4 + 4];
        CVT_TF32(wah[kt][0], f0); wal[kt][0] = __float_as_uint(f0 - __uint_as_float(wah[kt][0]));
        CVT_TF32(wah[kt][1], f1); wal[kt][1] = __float_as_uint(f1 - __uint_as_float(wah[kt][1]));
        CVT_TF32(wah[kt][2], f2); wal[kt][2] = __float_as_uint(f2 - __uint_as_float(wah[kt][2]));
        CVT_TF32(wah[kt][3], f3); wal[kt][3] = __float_as_uint(f3 - __uint_as_float(wah[kt][3]));
    }
    const float bz0 = bo[row0];
    const float bz1 = bo[row1];

    // Stage X = op0 + op1 tile hi/lo (64 ch x 16 cols)
    for (int i = tid; i < 1024; i += 256) {
        const int ch = i >> 4, c = i & 15;
        const size_t idx = ((size_t)(b * 64 + ch)) * LL + l0 + c;
        float f = g_op[0][idx] + g_op[1][idx];
        u32 hb; CVT_TF32(hb, f);
        float hi = __uint_as_float(hb);
        sXh[ch][c] = hi;
        sXl[ch][c] = f - hi;
    }
    __syncthreads();

    float gA0=0.f,gA1=0.f,gA2=0.f,gA3=0.f;
    float gB0=0.f,gB1=0.f,gB2=0.f,gB3=0.f;
#pragma unroll
    for (int kt = 0; kt < 8; kt++) {
        const int kr = kt * 8;
        const u32 bh0 = __float_as_uint(sXh[kr + c4]    [nt * 8 + gid]);
        const u32 bh1 = __float_as_uint(sXh[kr + c4 + 4][nt * 8 + gid]);
        const u32 bl0 = __float_as_uint(sXl[kr + c4]    [nt * 8 + gid]);
        const u32 bl1 = __float_as_uint(sXl[kr + c4 + 4][nt * 8 + gid]);
        MMA_TF32(gA0,gA1,gA2,gA3, wah[kt][0],wah[kt][1],wah[kt][2],wah[kt][3], bh0,bh1);
        MMA_TF32(gB0,gB1,gB2,gB3, wah[kt][0],wah[kt][1],wah[kt][2],wah[kt][3], bl0,bl1);
        MMA_TF32(gB0,gB1,gB2,gB3, wal[kt][0],wal[kt][1],wal[kt][2],wal[kt][3], bh0,bh1);
    }
    const int n = l0 + nt * 8 + 2 * c4;
    const size_t i00 = ((size_t)(b * 64 + row0)) * LL + n;
    const size_t i10 = ((size_t)(b * 64 + row1)) * LL + n;
    out[i00]     = gA0 + gB0 + bz0;
    out[i00 + 1] = gA1 + gB1 + bz0;
    out[i10]     = gA2 + gB2 + bz1;
    out[i10 + 1] = gA3 + gB3 + bz1;
}

// ---------------------------------------------------------------------------
extern "C" void kernel_launch(void* const* d_in, const int* in_sizes, int n_in,
                              void* d_out, int out_size)
{
    const float* x  = (const float*)d_in[0];
    const float* Wq = (const float*)d_in[1];
    const float* bq = (const float*)d_in[2];
    const float* Wk = (const float*)d_in[3];
    const float* bk = (const float*)d_in[4];
    const float* Wv = (const float*)d_in[5];
    const float* bv = (const float*)d_in[6];
    const float* Wo = (const float*)d_in[7];
    const float* bo = (const float*)d_in[8];

    float* out   = (float*)d_out;           // first output: conv result
    float* q_out = (float*)d_out + BCHL;    // second output: scaled q

    k_qkv<<<144, 384>>>(x, Wq, bq, Wk, bk, Wv, bv, q_out);
    k_passA<<<dim3(16, 18, 2), 256>>>();
    k_passB<<<dim3(16, 18, 2), 256>>>();
    k_oconv<<<288, 256>>>(Wo, bo, out);
}

// round 17
// speedup vs baseline: 1.0997x; 1.0556x over previous
#include <cuda_runtime.h>
#include <cuda_fp16.h>

// Problem constants (fixed by the reference setup)
#define BB   2
#define CH   64
#define NH   8
#define DH   8
#define HW   48
#define LL   2304            // HW*HW
#define BCHL (BB*CH*LL)      // 294912

#define LOG2E 1.4426950408889634f

#define EX2F(r,x)     asm("ex2.approx.ftz.f32 %0,%1;"  : "=f"(r) : "f"(x))
#define CVT_TF32(u,x) asm("cvt.rna.tf32.f32 %0,%1;"    : "=r"(u) : "f"(x))
// d = {hi=cvt(a), lo=cvt(b)}
#define PACK_F16X2(d,a,b) asm("cvt.rn.f16x2.f32 %0,%1,%2;" : "=r"(d) : "f"(a), "f"(b))

#define MMA_TF32(d0,d1,d2,d3,a0,a1,a2,a3,b0,b1) \
  asm volatile("mma.sync.aligned.m16n8k8.row.col.f32.tf32.tf32.f32 " \
    "{%0,%1,%2,%3},{%4,%5,%6,%7},{%8,%9},{%0,%1,%2,%3};" \
    : "+f"(d0),"+f"(d1),"+f"(d2),"+f"(d3) \
    : "r"(a0),"r"(a1),"r"(a2),"r"(a3),"r"(b0),"r"(b1))

#define MMA_F16(d0,d1,d2,d3,a0,a1,a2,a3,b0,b1) \
  asm volatile("mma.sync.aligned.m16n8k16.row.col.f32.f16.f16.f32 " \
    "{%0,%1,%2,%3},{%4,%5,%6,%7},{%8,%9},{%0,%1,%2,%3};" \
    : "+f"(d0),"+f"(d1),"+f"(d2),"+f"(d3) \
    : "r"(a0),"r"(a1),"r"(a2),"r"(a3),"r"(b0),"r"(b1))

typedef unsigned int u32;

// Scratch (device globals — no allocation allowed)
__device__ float g_q [BCHL];          // q * d^-0.5 * log2(e)  (for EX2)
__device__ float g_k [BCHL];
__device__ float g_v [BCHL];
__device__ float g_Z [2][BB*NH][LL];  // 2 q-split partials
__device__ float g_op[2][BCHL];

// ---------------------------------------------------------------------------
// K1: q/k/v 1x1 convs as tf32 tensor GEMM.  grid = 144 x 384 (12 warps),
// 32 cols/block.  Warp (m_idx = wid>>2 in {q,k,v}, mtile = wid&3).
// ---------------------------------------------------------------------------
__global__ __launch_bounds__(384) void k_qkv(
    const float* __restrict__ x,
    const float* __restrict__ Wq, const float* __restrict__ bq,
    const float* __restrict__ Wk, const float* __restrict__ bk,
    const float* __restrict__ Wv, const float* __restrict__ bv,
    float* __restrict__ q_out)
{
    __shared__ float sXh[64][40], sXl[64][40];
    const int tid  = threadIdx.x;
    const int lane = tid & 31, wid = tid >> 5;
    const int c4 = lane & 3, gid = lane >> 2;
    const int m_idx = wid >> 2;          // 0=q, 1=k, 2=v
    const int mtile = wid & 3;           // 16-row tile of W

    const int b  = blockIdx.x / 72;
    const int l0 = (blockIdx.x - b * 72) * 32;

    const float qscale = 0.35355339059327373f;  // 8^-0.5
    const float* Wm = (m_idx == 0) ? Wq : (m_idx == 1) ? Wk : Wv;
    const float* bm = (m_idx == 0) ? bq : (m_idx == 1) ? bk : bv;
    const float wsc = (m_idx == 0) ? qscale : 1.0f;

    const int row0 = mtile * 16 + gid;
    const int row1 = row0 + 8;

    // A-fragments for all 8 k-tiles (hi/lo)
    u32 wah[8][4], wal[8][4];
#pragma unroll
    for (int kt = 0; kt < 8; kt++) {
        const int k0 = kt * 8;
        float f0 = Wm[row0 * 64 + k0 + c4]     * wsc;
        float f1 = Wm[row1 * 64 + k0 + c4]     * wsc;
        float f2 = Wm[row0 * 64 + k0 + c4 + 4] * wsc;
        float f3 = Wm[row1 * 64 + k0 + c4 + 4] * wsc;
        CVT_TF32(wah[kt][0], f0); wal[kt][0] = __float_as_uint(f0 - __uint_as_float(wah[kt][0]));
        CVT_TF32(wah[kt][1], f1); wal[kt][1] = __float_as_uint(f1 - __uint_as_float(wah[kt][1]));
        CVT_TF32(wah[kt][2], f2); wal[kt][2] = __float_as_uint(f2 - __uint_as_float(wah[kt][2]));
        CVT_TF32(wah[kt][3], f3); wal[kt][3] = __float_as_uint(f3 - __uint_as_float(wah[kt][3]));
    }
    const float bz0 = bm[row0] * wsc;
    const float bz1 = bm[row1] * wsc;

    // Stage X tile hi/lo (64 ch x 32 cols)
    for (int i = tid; i < 2048; i += 384) {
        const int ch = i >> 5, c = i & 31;
        float f = x[((size_t)(b * 64 + ch)) * LL + l0 + c];
        u32 hb; CVT_TF32(hb, f);
        float hi = __uint_as_float(hb);
        sXh[ch][c] = hi;
        sXl[ch][c] = f - hi;
    }
    __syncthreads();

    float* dst = (m_idx == 0) ? g_q : (m_idx == 1) ? g_k : g_v;

#pragma unroll
    for (int nt = 0; nt < 4; nt++) {
        float gA0=0.f,gA1=0.f,gA2=0.f,gA3=0.f;   // Wh*Xh
        float gB0=0.f,gB1=0.f,gB2=0.f,gB3=0.f;   // cross terms
#pragma unroll
        for (int kt = 0; kt < 8; kt++) {
            const int kr = kt * 8;
            const u32 bh0 = __float_as_uint(sXh[kr + c4]    [nt * 8 + gid]);
            const u32 bh1 = __float_as_uint(sXh[kr + c4 + 4][nt * 8 + gid]);
            const u32 bl0 = __float_as_uint(sXl[kr + c4]    [nt * 8 + gid]);
            const u32 bl1 = __float_as_uint(sXl[kr + c4 + 4][nt * 8 + gid]);
            MMA_TF32(gA0,gA1,gA2,gA3, wah[kt][0],wah[kt][1],wah[kt][2],wah[kt][3], bh0,bh1);
            MMA_TF32(gB0,gB1,gB2,gB3, wah[kt][0],wah[kt][1],wah[kt][2],wah[kt][3], bl0,bl1);
            MMA_TF32(gB0,gB1,gB2,gB3, wal[kt][0],wal[kt][1],wal[kt][2],wal[kt][3], bh0,bh1);
        }
        const float c0 = gA0 + gB0 + bz0;
        const float c1 = gA1 + gB1 + bz0;
        const float c2 = gA2 + gB2 + bz1;
        const float c3 = gA3 + gB3 + bz1;

        const int n = l0 + nt * 8 + 2 * c4;
        const size_t i00 = ((size_t)(b * 64 + row0)) * LL + n;
        const size_t i10 = ((size_t)(b * 64 + row1)) * LL + n;
        if (m_idx == 0) {
            q_out[i00]     = c0;  q_out[i00 + 1] = c1;
            q_out[i10]     = c2;  q_out[i10 + 1] = c3;
            dst[i00]     = c0 * LOG2E;  dst[i00 + 1] = c1 * LOG2E;
            dst[i10]     = c2 * LOG2E;  dst[i10 + 1] = c3 * LOG2E;
        } else {
            dst[i00]     = c0;  dst[i00 + 1] = c1;
            dst[i10]     = c2;  dst[i10 + 1] = c3;
        }
    }
}

// ---------------------------------------------------------------------------
// K2 (pass A): tensor-core Z with split logit chains + double-buffered SMEM
// pipeline (register prefetch of chunk+1's Q loads under chunk's compute;
// one sync per iteration).  grid = (bh=16, kblk=18, qseg=2) x 256 thr.
// ---------------------------------------------------------------------------
__global__ __launch_bounds__(256) void k_passA()
{
    const int bh = blockIdx.x;
    const int b = bh >> 3, h = bh & 7;
    const size_t base = (size_t)(b * CH + h * DH) * LL;
    const int tid  = threadIdx.x;
    const int lane = tid & 31, wid = tid >> 5;
    const int c4 = lane & 3, gid = lane >> 2;
    const int wk = blockIdx.y * 128 + wid * 16;  // this warp's 16 k-cols
    const int qs = blockIdx.z;

    // Two fixed B-fragment groups (K hi/lo), cols [wk,wk+8) and [wk+8,wk+16)
    u32 bhA0, bhA1, blA0, blA1, bhB0, bhB1, blB0, blB1;
    {
        float f;
        f = g_k[base + (size_t)c4       * LL + wk + gid];
        CVT_TF32(bhA0, f); blA0 = __float_as_uint(f - __uint_as_float(bhA0));
        f = g_k[base + (size_t)(c4 + 4) * LL + wk + gid];
        CVT_TF32(bhA1, f); blA1 = __float_as_uint(f - __uint_as_float(bhA1));
        f = g_k[base + (size_t)c4       * LL + wk + 8 + gid];
        CVT_TF32(bhB0, f); blB0 = __float_as_uint(f - __uint_as_float(bhB0));
        f = g_k[base + (size_t)(c4 + 4) * LL + wk + 8 + gid];
        CVT_TF32(bhB1, f); blB1 = __float_as_uint(f - __uint_as_float(bhB1));
    }

    __shared__ float sqh[2][8][136], sql[2][8][136];

    // Each thread owns 4 (d, qq) slots: i = tid + j*256 -> d = i>>7, qq = i&127
    const int fd[4]  = { tid >> 7, (tid + 256) >> 7, (tid + 512) >> 7, (tid + 768) >> 7 };
    const int fqq    = tid & 127;   // same for all 4 (256-stride keeps qq fixed)

    float pq[4];
    // load + store chunk 0 into buffer 0
    {
        const int q0 = qs * 1152;
#pragma unroll
        for (int j = 0; j < 4; j++)
            pq[j] = g_q[base + (size_t)fd[j] * LL + q0 + fqq];
#pragma unroll
        for (int j = 0; j < 4; j++) {
            u32 hb; CVT_TF32(hb, pq[j]);
            float hi = __uint_as_float(hb);
            sqh[0][fd[j]][fqq] = hi;
            sql[0][fd[j]][fqq] = pq[j] - hi;
        }
    }
    __syncthreads();

    float zA0 = 0.f, zA1 = 0.f, zB0 = 0.f, zB1 = 0.f;

    for (int chunk = 0; chunk < 9; chunk++) {
        const int cur = chunk & 1;

        // prefetch next chunk's Q (latency hidden under compute)
        if (chunk < 8) {
            const int q0 = qs * 1152 + (chunk + 1) * 128;
#pragma unroll
            for (int j = 0; j < 4; j++)
                pq[j] = g_q[base + (size_t)fd[j] * LL + q0 + fqq];
        }

#pragma unroll
        for (int qt = 0; qt < 8; qt++) {
            const int qq = qt * 16 + gid;
            const u32 ah0 = __float_as_uint(sqh[cur][c4][qq]);
            const u32 ah1 = __float_as_uint(sqh[cur][c4][qq + 8]);
            const u32 ah2 = __float_as_uint(sqh[cur][c4 + 4][qq]);
            const u32 ah3 = __float_as_uint(sqh[cur][c4 + 4][qq + 8]);
            const u32 al0 = __float_as_uint(sql[cur][c4][qq]);
            const u32 al1 = __float_as_uint(sql[cur][c4][qq + 8]);
            const u32 al2 = __float_as_uint(sql[cur][c4 + 4][qq]);
            const u32 al3 = __float_as_uint(sql[cur][c4 + 4][qq + 8]);

            float pAH0=0.f,pAH1=0.f,pAH2=0.f,pAH3=0.f;
            float pAL0=0.f,pAL1=0.f,pAL2=0.f,pAL3=0.f;
            float pBH0=0.f,pBH1=0.f,pBH2=0.f,pBH3=0.f;
            float pBL0=0.f,pBL1=0.f,pBL2=0.f,pBL3=0.f;
            MMA_TF32(pAH0,pAH1,pAH2,pAH3, ah0,ah1,ah2,ah3, bhA0,bhA1);
            MMA_TF32(pBH0,pBH1,pBH2,pBH3, ah0,ah1,ah2,ah3, bhB0,bhB1);
            MMA_TF32(pAL0,pAL1,pAL2,pAL3, ah0,ah1,ah2,ah3, blA0,blA1);
            MMA_TF32(pBL0,pBL1,pBL2,pBL3, ah0,ah1,ah2,ah3, blB0,blB1);
            MMA_TF32(pAL0,pAL1,pAL2,pAL3, al0,al1,al2,al3, bhA0,bhA1);
            MMA_TF32(pBL0,pBL1,pBL2,pBL3, al0,al1,al2,al3, bhB0,bhB1);

            float e0,e1,e2,e3,f0,f1,f2,f3;
            EX2F(e0, pAH0 + pAL0); EX2F(e1, pAH1 + pAL1);
            EX2F(e2, pAH2 + pAL2); EX2F(e3, pAH3 + pAL3);
            EX2F(f0, pBH0 + pBL0); EX2F(f1, pBH1 + pBL1);
            EX2F(f2, pBH2 + pBL2); EX2F(f3, pBH3 + pBL3);
            zA0 += e0 + e2;   // col wk + 2c4
            zA1 += e1 + e3;   // col wk + 2c4 + 1
            zB0 += f0 + f2;   // col wk + 8 + 2c4
            zB1 += f1 + f3;   // col wk + 8 + 2c4 + 1
        }

        // store prefetched chunk into the other buffer, then one sync
        if (chunk < 8) {
            const int nb = cur ^ 1;
#pragma unroll
            for (int j = 0; j < 4; j++) {
                u32 hb; CVT_TF32(hb, pq[j]);
                float hi = __uint_as_float(hb);
                sqh[nb][fd[j]][fqq] = hi;
                sql[nb][fd[j]][fqq] = pq[j] - hi;
            }
            __syncthreads();
        }
    }

    // reduce over the 8 gid-lanes sharing each column (lanes with same c4)
    zA0 += __shfl_xor_sync(0xffffffffu, zA0, 4);
    zA0 += __shfl_xor_sync(0xffffffffu, zA0, 8);
    zA0 += __shfl_xor_sync(0xffffffffu, zA0, 16);
    zA1 += __shfl_xor_sync(0xffffffffu, zA1, 4);
    zA1 += __shfl_xor_sync(0xffffffffu, zA1, 8);
    zA1 += __shfl_xor_sync(0xffffffffu, zA1, 16);
    zB0 += __shfl_xor_sync(0xffffffffu, zB0, 4);
    zB0 += __shfl_xor_sync(0xffffffffu, zB0, 8);
    zB0 += __shfl_xor_sync(0xffffffffu, zB0, 16);
    zB1 += __shfl_xor_sync(0xffffffffu, zB1, 4);
    zB1 += __shfl_xor_sync(0xffffffffu, zB1, 8);
    zB1 += __shfl_xor_sync(0xffffffffu, zB1, 16);

    if (lane < 4) {
        float* Zp = &g_Z[qs][bh][0];
        Zp[wk + 2 * lane]         = zA0;
        Zp[wk + 2 * lane + 1]     = zA1;
        Zp[wk + 8 + 2 * lane]     = zB0;
        Zp[wk + 8 + 2 * lane + 1] = zB1;
    }
}

// ---------------------------------------------------------------------------
// K3 (pass B): tensor-core, fused zinv, split chains, 4 AV accumulator
// groups + double-buffered pipeline (proven R16).
// grid = (bh=16, qblk=18, kseg=2) x 256 thr.
// ---------------------------------------------------------------------------
__global__ __launch_bounds__(256) void k_passB()
{
    const int bh = blockIdx.x;
    const int b = bh >> 3, h = bh & 7;
    const size_t base = (size_t)(b * CH + h * DH) * LL;
    const int tid  = threadIdx.x;
    const int lane = tid & 31, wid = tid >> 5;
    const int c4 = lane & 3, gid = lane >> 2;
    const int q0 = blockIdx.y * 128 + wid * 16;
    const int kseg = blockIdx.z;

    // Q A-fragments (tf32 hi + f32 residual), rows=q, cols=d
    u32 ah[4], al[4];
    {
        float f0 = g_q[base + (size_t)c4 * LL + q0 + gid];
        float f1 = g_q[base + (size_t)c4 * LL + q0 + gid + 8];
        float f2 = g_q[base + (size_t)(c4 + 4) * LL + q0 + gid];
        float f3 = g_q[base + (size_t)(c4 + 4) * LL + q0 + gid + 8];
        CVT_TF32(ah[0], f0); al[0] = __float_as_uint(f0 - __uint_as_float(ah[0]));
        CVT_TF32(ah[1], f1); al[1] = __float_as_uint(f1 - __uint_as_float(ah[1]));
        CVT_TF32(ah[2], f2); al[2] = __float_as_uint(f2 - __uint_as_float(ah[2]));
        CVT_TF32(ah[3], f3); al[3] = __float_as_uint(f3 - __uint_as_float(ah[3]));
    }

    __shared__ float  skhi[2][8][136], sklo[2][8][136];
    __shared__ __half svh [2][8][136], svl [2][8][136];

    const int fkk = tid & 127;      // fixed k column this thread fills
    const int fd0 = tid >> 7;       // starting row (0/1), step 2

    // prefetch registers
    float pzA, pzB, pk[4], pv[4];

    // load + store chunk 0 into buffer 0
    {
        const int kc = kseg * 1152;
        pzA = g_Z[0][bh][kc + fkk];
        pzB = g_Z[1][bh][kc + fkk];
#pragma unroll
        for (int j = 0; j < 4; j++) {
            const int d = fd0 + 2 * j;
            pk[j] = g_k[base + (size_t)d * LL + kc + fkk];
            pv[j] = g_v[base + (size_t)d * LL + kc + fkk];
        }
        const float zi = 1.0f / (pzA + pzB);
#pragma unroll
        for (int j = 0; j < 4; j++) {
            const int d = fd0 + 2 * j;
            u32 hb; CVT_TF32(hb, pk[j]);
            float hi = __uint_as_float(hb);
            skhi[0][d][fkk] = hi;
            sklo[0][d][fkk] = pk[j] - hi;
            float vv = pv[j] * zi;
            __half vh_ = __float2half_rn(vv);
            svh[0][d][fkk] = vh_;
            svl[0][d][fkk] = __float2half_rn(vv - __half2float(vh_));
        }
    }
    __syncthreads();

    // 4 independent accumulator groups
    float oA0=0.f,oA1=0.f,oA2=0.f,oA3=0.f;   // vh, even kt
    float oB0=0.f,oB1=0.f,oB2=0.f,oB3=0.f;   // vl, even kt
    float oC0=0.f,oC1=0.f,oC2=0.f,oC3=0.f;   // vh, odd kt
    float oD0=0.f,oD1=0.f,oD2=0.f,oD3=0.f;   // vl, odd kt

    for (int chunk = 0; chunk < 9; chunk++) {
        const int cur = chunk & 1;

        // prefetch next chunk's globals (latency hidden under compute)
        if (chunk < 8) {
            const int kc = kseg * 1152 + (chunk + 1) * 128;
            pzA = g_Z[0][bh][kc + fkk];
            pzB = g_Z[1][bh][kc + fkk];
#pragma unroll
            for (int j = 0; j < 4; j++) {
                const int d = fd0 + 2 * j;
                pk[j] = g_k[base + (size_t)d * LL + kc + fkk];
                pv[j] = g_v[base + (size_t)d * LL + kc + fkk];
            }
        }

#pragma unroll
        for (int kt = 0; kt < 8; kt++) {
            const int kx0 = kt * 16 + gid;
            const int kx1 = kx0 + 8;
            const u32 b00 = __float_as_uint(skhi[cur][c4][kx0]);
            const u32 b01 = __float_as_uint(skhi[cur][c4 + 4][kx0]);
            const u32 l00 = __float_as_uint(sklo[cur][c4][kx0]);
            const u32 l01 = __float_as_uint(sklo[cur][c4 + 4][kx0]);
            const u32 b10 = __float_as_uint(skhi[cur][c4][kx1]);
            const u32 b11 = __float_as_uint(skhi[cur][c4 + 4][kx1]);
            const u32 l10 = __float_as_uint(sklo[cur][c4][kx1]);
            const u32 l11 = __float_as_uint(sklo[cur][c4 + 4][kx1]);

            float pH0=0.f,pH1=0.f,pH2=0.f,pH3=0.f;
            float pL0=0.f,pL1=0.f,pL2=0.f,pL3=0.f;
            float rH0=0.f,rH1=0.f,rH2=0.f,rH3=0.f;
            float rL0=0.f,rL1=0.f,rL2=0.f,rL3=0.f;
            MMA_TF32(pH0,pH1,pH2,pH3, ah[0],ah[1],ah[2],ah[3], b00,b01);
            MMA_TF32(rH0,rH1,rH2,rH3, ah[0],ah[1],ah[2],ah[3], b10,b11);
            MMA_TF32(pL0,pL1,pL2,pL3, ah[0],ah[1],ah[2],ah[3], l00,l01);
            MMA_TF32(rL0,rL1,rL2,rL3, ah[0],ah[1],ah[2],ah[3], l10,l11);
            MMA_TF32(pL0,pL1,pL2,pL3, al[0],al[1],al[2],al[3], b00,b01);
            MMA_TF32(rL0,rL1,rL2,rL3, al[0],al[1],al[2],al[3], b10,b11);

            float e0,e1,e2,e3,f0,f1,f2,f3;
            EX2F(e0, pH0 + pL0); EX2F(e1, pH1 + pL1);
            EX2F(e2, pH2 + pL2); EX2F(e3, pH3 + pL3);
            EX2F(f0, rH0 + rL0); EX2F(f1, rH1 + rL1);
            EX2F(f2, rH2 + rL2); EX2F(f3, rH3 + rL3);

            u32 wh0, wh1, wh2, wh3;
            PACK_F16X2(wh0, e1, e0);
            PACK_F16X2(wh1, e3, e2);
            PACK_F16X2(wh2, f1, f0);
            PACK_F16X2(wh3, f3, f2);

            const u32 vh0 = *reinterpret_cast<const u32*>(&svh[cur][gid][kt * 16 + 2 * c4]);
            const u32 vh1 = *reinterpret_cast<const u32*>(&svh[cur][gid][kt * 16 + 2 * c4 + 8]);
            const u32 vl0 = *reinterpret_cast<const u32*>(&svl[cur][gid][kt * 16 + 2 * c4]);
            const u32 vl1 = *reinterpret_cast<const u32*>(&svl[cur][gid][kt * 16 + 2 * c4 + 8]);

            if (kt & 1) {
                MMA_F16(oC0,oC1,oC2,oC3, wh0,wh1,wh2,wh3, vh0,vh1);
                MMA_F16(oD0,oD1,oD2,oD3, wh0,wh1,wh2,wh3, vl0,vl1);
            } else {
                MMA_F16(oA0,oA1,oA2,oA3, wh0,wh1,wh2,wh3, vh0,vh1);
                MMA_F16(oB0,oB1,oB2,oB3, wh0,wh1,wh2,wh3, vl0,vl1);
            }
        }

        // store prefetched chunk into the other buffer, then one sync
        if (chunk < 8) {
            const int nb = cur ^ 1;
            const float zi = 1.0f / (pzA + pzB);
#pragma unroll
            for (int j = 0; j < 4; j++) {
                const int d = fd0 + 2 * j;
                u32 hb; CVT_TF32(hb, pk[j]);
                float hi = __uint_as_float(hb);
                skhi[nb][d][fkk] = hi;
                sklo[nb][d][fkk] = pk[j] - hi;
                float vv = pv[j] * zi;
                __half vh_ = __float2half_rn(vv);
                svh[nb][d][fkk] = vh_;
                svl[nb][d][fkk] = __float2half_rn(vv - __half2float(vh_));
            }
            __syncthreads();
        }
    }

    const float oc0 = (oA0 + oB0) + (oC0 + oD0);
    const float oc1 = (oA1 + oB1) + (oC1 + oD1);
    const float oc2 = (oA2 + oB2) + (oC2 + oD2);
    const float oc3 = (oA3 + oB3) + (oC3 + oD3);

    float* Ob = g_op[kseg] + base;
    Ob[(size_t)(2 * c4)     * LL + q0 + gid]     = oc0;
    Ob[(size_t)(2 * c4 + 1) * LL + q0 + gid]     = oc1;
    Ob[(size_t)(2 * c4)     * LL + q0 + gid + 8] = oc2;
    Ob[(size_t)(2 * c4 + 1) * LL + q0 + gid + 8] = oc3;
}

// ---------------------------------------------------------------------------
// K4: output 1x1 conv as tf32 tensor GEMM with fused 2-partial reduction.
// grid = 288 x 256 (8 warps; 16 cols per block; warp = mtile x n-tile).
// ---------------------------------------------------------------------------
__global__ __launch_bounds__(256) void k_oconv(
    const float* __restrict__ Wo, const float* __restrict__ bo,
    float* __restrict__ out)
{
    __shared__ float sXh[64][40], sXl[64][40];
    const int tid  = threadIdx.x;
    const int lane = tid & 31, wid = tid >> 5;
    const int c4 = lane & 3, gid = lane >> 2;
    const int mtile = wid & 3;
    const int nt    = wid >> 2;          // 0/1: which 8-col tile

    const int b  = blockIdx.x / 144;
    const int l0 = (blockIdx.x - b * 144) * 16;

    const int row0 = mtile * 16 + gid;
    const int row1 = row0 + 8;

    // A-fragments for all 8 k-tiles (hi/lo)
    u32 wah[8][4], wal[8][4];
#pragma unroll
    for (int kt = 0; kt < 8; kt++) {
        const int k0 = kt * 8;
        float f0 = Wo[row0 * 64 + k0 + c4];
        float f1 = Wo[row1 * 64 + k0 + c4];
        float f2 = Wo[row0 * 64 + k0 + c4 + 4];
        float f3 = Wo[row1 * 64 + k0 + c4 + 4];
        CVT_TF32(wah[kt][0], f0); wal[kt][0] = __float_as_uint(f0 - __uint_as_float(wah[kt][0]));
        CVT_TF32(wah[kt][1], f1); wal[kt][1] = __float_as_uint(f1 - __uint_as_float(wah[kt][1]));
        CVT_TF32(wah[kt][2], f2); wal[kt][2] = __float_as_uint(f2 - __uint_as_float(wah[kt][2]));
        CVT_TF32(wah[kt][3], f3); wal[kt][3] = __float_as_uint(f3 - __uint_as_float(wah[kt][3]));
    }
    const float bz0 = bo[row0];
    const float bz1 = bo[row1];

    // Stage X = op0 + op1 tile hi/lo (64 ch x 16 cols)
#pragma unroll
    for (int i = tid; i < 1024; i += 256) {
        const int ch = i >> 4, c = i & 15;
        const size_t idx = ((size_t)(b * 64 + ch)) * LL + l0 + c;
        float f = g_op[0][idx] + g_op[1][idx];
        u32 hb; CVT_TF32(hb, f);
        float hi = __uint_as_float(hb);
        sXh[ch][c] = hi;
        sXl[ch][c] = f - hi;
    }
    __syncthreads();

    float gA0=0.f,gA1=0.f,gA2=0.f,gA3=0.f;
    float gB0=0.f,gB1=0.f,gB2=0.f,gB3=0.f;
#pragma unroll
    for (int kt = 0; kt < 8; kt++) {
        const int kr = kt * 8;
        const u32 bh0 = __float_as_uint(sXh[kr + c4]    [nt * 8 + gid]);
        const u32 bh1 = __float_as_uint(sXh[kr + c4 + 4][nt * 8 + gid]);
        const u32 bl0 = __float_as_uint(sXl[kr + c4]    [nt * 8 + gid]);
        const u32 bl1 = __float_as_uint(sXl[kr + c4 + 4][nt * 8 + gid]);
        MMA_TF32(gA0,gA1,gA2,gA3, wah[kt][0],wah[kt][1],wah[kt][2],wah[kt][3], bh0,bh1);
        MMA_TF32(gB0,gB1,gB2,gB3, wah[kt][0],wah[kt][1],wah[kt][2],wah[kt][3], bl0,bl1);
        MMA_TF32(gB0,gB1,gB2,gB3, wal[kt][0],wal[kt][1],wal[kt][2],wal[kt][3], bh0,bh1);
    }
    const int n = l0 + nt * 8 + 2 * c4;
    const size_t i00 = ((size_t)(b * 64 + row0)) * LL + n;
    const size_t i10 = ((size_t)(b * 64 + row1)) * LL + n;
    out[i00]     = gA0 + gB0 + bz0;
    out[i00 + 1] = gA1 + gB1 + bz0;
    out[i10]     = gA2 + gB2 + bz1;
    out[i10 + 1] = gA3 + gB3 + bz1;
}

// ---------------------------------------------------------------------------
extern "C" void kernel_launch(void* const* d_in, const int* in_sizes, int n_in,
                              void* d_out, int out_size)
{
    const float* x  = (const float*)d_in[0];
    const float* Wq = (const float*)d_in[1];
    const float* bq = (const float*)d_in[2];
    const float* Wk = (const float*)d_in[3];
    const float* bk = (const float*)d_in[4];
    const float* Wv = (const float*)d_in[5];
    const float* bv = (const float*)d_in[6];
    const float* Wo = (const float*)d_in[7];
    const float* bo = (const float*)d_in[8];

    float* out   = (float*)d_out;           // first output: conv result
    float* q_out = (float*)d_out + BCHL;    // second output: scaled q

    k_qkv<<<144, 384>>>(x, Wq, bq, Wk, bk, Wv, bv, q_out);
    k_passA<<<dim3(16, 18, 2), 256>>>();
    k_passB<<<dim3(16, 18, 2), 256>>>();
    k_oconv<<<288, 256>>>(Wo, bo, out);
}